// round 16
// baseline (speedup 1.0000x reference)
#include <cuda_runtime.h>
#include <math.h>
#include <stdint.h>

#define BATCH 2
#define CH    512
#define HH    128
#define WW    128
#define NPIX  (HH*WW)        // 16384
#define MROWS (BATCH*NPIX)   // 32768
#define HEADS 8
#define HDIM  64
#define PTS   4
#define LNUM  6
#define NOA   96             // 64 offset cols + 32 attn cols

// ---------------- device scratch (no allocations allowed) ----------------
static __device__ float g_q   [MROWS*CH];   // exact residual stream
static __device__ float g_qr  [MROWS*CH];   // tf32-rounded copy of LN1 output (GEMM A)
static __device__ float g_qpos[MROWS*CH];
static __device__ float g_x   [MROWS*CH];   // round(q + qpos) (GEMM A)
static __device__ float g_feat[MROWS*CH];
static __device__ float g_v   [MROWS*CH];
static __device__ float g_b1  [MROWS*CH];
static __device__ float g_b2  [MROWS*CH];
static __device__ float g_oa  [MROWS*NOA];
static __device__ float g_ref [MROWS*2];
static __device__ float g_wcat[LNUM*NOA*CH];   // transposed: [l][n][k]
static __device__ float g_bcat[LNUM*NOA];
static __device__ float g_wvT  [LNUM*CH*CH];   // [l][n][k]
static __device__ float g_woutT[LNUM*CH*CH];
static __device__ float g_w1T  [LNUM*CH*CH];
static __device__ float g_w2T  [LNUM*CH*CH];
static __device__ float g_pe2T [CH*CH];
static __device__ int   g_valid [MROWS];
static __device__ int   g_order [MROWS];
static __device__ int   g_validp[MROWS];
static __device__ int   g_rank  [MROWS];

__device__ __forceinline__ float to_tf32(float x) {
    float r;
    asm("cvt.rna.tf32.f32 %0, %1;" : "=f"(r) : "f"(x));
    return r;
}
__device__ __forceinline__ uint32_t smem_u32(const void* p) {
    uint32_t a;
    asm("{ .reg .u64 t; cvta.to.shared.u64 t, %1; cvt.u32.u64 %0, t; }" : "=r"(a) : "l"(p));
    return a;
}
__device__ __forceinline__ void cpa16(uint32_t s, const void* g) {
    asm volatile("cp.async.cg.shared.global [%0], [%1], 16;" :: "r"(s), "l"(g));
}

// ---------------- tiled transpose (optional tf32 rounding): src[B][R][Cc] -> dst[B][Cc][R] ----------------
template<int RND>
__global__ void k_tr(const float* __restrict__ src, float* __restrict__ dst, int R, int Cc) {
    __shared__ float t[32][33];
    int b  = blockIdx.z;
    int c0 = blockIdx.x * 32, r0 = blockIdx.y * 32;
    int tx = threadIdx.x, ty = threadIdx.y;   // 32 x 8
    const float* s = src + (size_t)b * R * Cc;
    float*       d = dst + (size_t)b * R * Cc;
    #pragma unroll
    for (int i = 0; i < 32; i += 8) {
        float v = s[(size_t)(r0 + ty + i) * Cc + c0 + tx];
        t[ty + i][tx] = RND ? to_tf32(v) : v;
    }
    __syncthreads();
    #pragma unroll
    for (int i = 0; i < 32; i += 8)
        d[(size_t)(c0 + ty + i) * R + r0 + tx] = t[tx][ty + i];
}

// ---------------- validity from row-major [B][N][C]: all 512 nonzero ----------------
__global__ void k_validity(const float* __restrict__ t) {
    int row = blockIdx.x;
    int tid = threadIdx.x;          // 128
    float4 v = *(const float4*)(t + (size_t)row * CH + tid * 4);
    int ok = (v.x != 0.0f) & (v.y != 0.0f) & (v.z != 0.0f) & (v.w != 0.0f);
    ok = __all_sync(~0u, ok);
    __shared__ int s[4];
    if ((tid & 31) == 0) s[tid >> 5] = ok;
    __syncthreads();
    if (tid == 0) g_valid[row] = s[0] & s[1] & s[2] & s[3];
}

// ---------------- stable partition (valid-first) via block scan ----------------
__global__ void k_scan() {
    int b = blockIdx.x;
    int tid = threadIdx.x;
    __shared__ int sd[1024];
    __shared__ int sbase;
    if (tid == 0) sbase = 0;
    __syncthreads();
    for (int c = 0; c < NPIX / 1024; c++) {
        int i = c * 1024 + tid;
        int v = g_valid[b * NPIX + i];
        sd[tid] = v;
        __syncthreads();
        for (int off = 1; off < 1024; off <<= 1) {
            int t = (tid >= off) ? sd[tid - off] : 0;
            __syncthreads();
            sd[tid] += t;
            __syncthreads();
        }
        g_rank[b * NPIX + i] = sbase + sd[tid] - v;
        __syncthreads();
        if (tid == 1023) sbase += sd[1023];
        __syncthreads();
    }
    int total = sbase;
    for (int c = 0; c < NPIX / 1024; c++) {
        int i = c * 1024 + tid;
        int v = g_valid[b * NPIX + i];
        int r = g_rank[b * NPIX + i];
        int pos = v ? r : (total + i - r);
        g_order [b * NPIX + pos] = i;
        g_validp[b * NPIX + pos] = v;
    }
}

__global__ void k_ref() {
    int i = blockIdx.x * blockDim.x + threadIdx.x;
    if (i >= MROWS) return;
    int n = g_order[i];
    float m = g_validp[i] ? 1.0f : 0.0f;
    g_ref[i * 2 + 0] = ((float)(n % WW) / (float)WW) * m;
    g_ref[i * 2 + 1] = ((float)(n / WW) / (float)HH) * m;
}

// ---------------- permute rows of [B][N][C] into packed order (exact) ----------------
__global__ void k_permq(const float* __restrict__ t, float* __restrict__ dst) {
    int idx = blockIdx.x * blockDim.x + threadIdx.x;   // float4 units
    if (idx >= MROWS * 128) return;
    int row = idx >> 7, c4 = idx & 127;
    int n = g_order[row];
    int b = row >> 14;
    float4 v = make_float4(0.f, 0.f, 0.f, 0.f);
    if (g_validp[row])
        v = *(const float4*)(t + ((size_t)(b * NPIX + n)) * CH + c4 * 4);
    *(float4*)(dst + (size_t)row * CH + c4 * 4) = v;
}

// ---------------- scatter packed rows back to dense [B][N][C] ----------------
__global__ void k_scatrows(const float* __restrict__ q, float* __restrict__ t) {
    int idx = blockIdx.x * blockDim.x + threadIdx.x;
    if (idx >= MROWS * 128) return;
    int row = idx >> 7, c4 = idx & 127;
    int n = g_order[row];
    int b = row >> 14;
    float4 v = make_float4(0.f, 0.f, 0.f, 0.f);
    if (g_validp[row])
        v = *(const float4*)(q + (size_t)row * CH + c4 * 4);
    *(float4*)(t + ((size_t)(b * NPIX + n)) * CH + c4 * 4) = v;
}

// ---------------- x = round(a + b) (float4) ----------------
__global__ void k_add(const float* __restrict__ a, const float* __restrict__ b,
                      float* __restrict__ o) {
    int idx = blockIdx.x * blockDim.x + threadIdx.x;
    if (idx >= MROWS * 128) return;
    float4 va = *(const float4*)(a + (size_t)idx * 4);
    float4 vb = *(const float4*)(b + (size_t)idx * 4);
    va.x = to_tf32(va.x + vb.x); va.y = to_tf32(va.y + vb.y);
    va.z = to_tf32(va.z + vb.z); va.w = to_tf32(va.w + vb.w);
    *(float4*)(o + (size_t)idx * 4) = va;
}

// ---------------- concat Woff|Waw -> transposed [l][n][k] (rounded) + biases ----------------
__global__ void k_concat(const float* __restrict__ Woff, const float* __restrict__ boff,
                         const float* __restrict__ Waw,  const float* __restrict__ baw) {
    int idx = blockIdx.x * blockDim.x + threadIdx.x;
    if (idx < LNUM * NOA * CH) {
        int k = idx & (CH - 1);
        int j = (idx >> 9) % NOA;
        int l = idx / (NOA * CH);
        float w = (j < 64) ? Woff[((size_t)l * CH + k) * 64 + j]
                           : Waw [((size_t)l * CH + k) * 32 + (j - 64)];
        g_wcat[idx] = to_tf32(w);
    }
    if (idx < LNUM * NOA) {
        int j = idx % NOA, l = idx / NOA;
        g_bcat[idx] = (j < 64) ? boff[l * 64 + j] : baw[l * 32 + (j - 64)];
    }
}

// ---------------- positional embedding: ref@peW1 -> BN(eval) -> relu (rounded) ----------------
__global__ void k_pe(const float* __restrict__ peW1, const float* __restrict__ g,
                     const float* __restrict__ bb, const float* __restrict__ m,
                     const float* __restrict__ vv) {
    int idx = blockIdx.x * blockDim.x + threadIdx.x;
    if (idx >= MROWS * CH) return;
    int c   = idx & (CH - 1);
    int row = idx >> 9;
    float rx = g_ref[row * 2], ry = g_ref[row * 2 + 1];
    float p = rx * peW1[c] + ry * peW1[CH + c];
    p = (p - m[c]) * rsqrtf(vv[c] + 1e-5f) * g[c] + bb[c];
    g_b1[idx] = to_tf32(fmaxf(p, 0.0f));
}

// ================= tf32 mma.sync GEMM, 64x64 warp tiles, cp.async 2-stage =================
// C[M,Ncols] = A[M,512] @ Bt[Ncols,512]^T  (+bias)(+Res)(relu?)
// CTA tile 128x128, 4 warps (2x2) of 64x64, BK=32, m16n8k8 tf32.
// Operands are PRE-ROUNDED to tf32 in gmem -> no cvt in the kernel.
// Both tiles K-major [128 rows][32 k], stride 36 (bank pattern 4g+tg: conflict-free).
__device__ __forceinline__ void mma_tf32(float c[4], const uint32_t a[4],
                                         uint32_t b0, uint32_t b1) {
    asm volatile(
        "mma.sync.aligned.m16n8k8.row.col.f32.tf32.tf32.f32 "
        "{%0,%1,%2,%3}, {%4,%5,%6,%7}, {%8,%9}, {%0,%1,%2,%3};"
        : "+f"(c[0]), "+f"(c[1]), "+f"(c[2]), "+f"(c[3])
        : "r"(a[0]), "r"(a[1]), "r"(a[2]), "r"(a[3]), "r"(b0), "r"(b1));
}

#define TS 36                      // tile row stride in floats
#define STAGEF (128 * TS)          // floats per operand stage
#define GEMM_SMEM (4 * STAGEF * (int)sizeof(float))   // 2 stages x (A + B) = 73728 B

template<int BIAS, int RES, int RELU>
__global__ __launch_bounds__(128)
void k_gemm(const float* __restrict__ A, const float* __restrict__ Bt,
            const float* __restrict__ bias, const float* __restrict__ Res,
            float* __restrict__ Cc, int Ncols) {
    extern __shared__ float sm[];
    // layout: A0 | B0 | A1 | B1
    int tid  = threadIdx.x;
    int warp = tid >> 5, lane = tid & 31;
    int g    = lane >> 2, tg = lane & 3;
    int warpM = warp & 1;            // 0..1 -> 64-row halves
    int warpN = warp >> 1;           // 0..1 -> 64-col halves
    int rowBase = blockIdx.y * 128;
    int colBase = blockIdx.x * 128;
    int nValid = Ncols - colBase; if (nValid > 128) nValid = 128;

    // per-thread load geometry: 8 x 16B chunks per operand per tile
    int ldr = tid >> 3;                  // base row (advance +16 per chunk)
    int kc  = (tid & 7) << 2;            // float col within 32

    auto load_tile = [&](int t) {
        int s = t & 1;
        int k0 = t * 32;
        float* as = sm + s * 2 * STAGEF;
        float* bs = as + STAGEF;
        #pragma unroll
        for (int p = 0; p < 8; p++) {
            int r = ldr + p * 16;
            cpa16(smem_u32(&as[r * TS + kc]),
                  A + (size_t)(rowBase + r) * 512 + k0 + kc);
            if (r < nValid)
                cpa16(smem_u32(&bs[r * TS + kc]),
                      Bt + (size_t)(colBase + r) * 512 + k0 + kc);
            else
                *(float4*)&bs[r * TS + kc] = make_float4(0.f, 0.f, 0.f, 0.f);
        }
        asm volatile("cp.async.commit_group;");
    };

    float acc[4][8][4];
    #pragma unroll
    for (int mi = 0; mi < 4; mi++)
        #pragma unroll
        for (int ni = 0; ni < 8; ni++)
            #pragma unroll
            for (int j = 0; j < 4; j++) acc[mi][ni][j] = 0.0f;

    load_tile(0);

    #pragma unroll 1
    for (int t = 0; t < 16; t++) {
        if (t < 15) {
            load_tile(t + 1);
            asm volatile("cp.async.wait_group 1;" ::: "memory");
        } else {
            asm volatile("cp.async.wait_group 0;" ::: "memory");
        }
        __syncthreads();
        const float* as = sm + (t & 1) * 2 * STAGEF;
        const float* bs = as + STAGEF;
        #pragma unroll
        for (int kk = 0; kk < 4; kk++) {
            int ks = kk * 8;
            uint32_t af[4][4];
            #pragma unroll
            for (int mi = 0; mi < 4; mi++) {
                int rb = warpM * 64 + mi * 16 + g;
                af[mi][0] = __float_as_uint(as[rb * TS + ks + tg]);
                af[mi][1] = __float_as_uint(as[(rb + 8) * TS + ks + tg]);
                af[mi][2] = __float_as_uint(as[rb * TS + ks + tg + 4]);
                af[mi][3] = __float_as_uint(as[(rb + 8) * TS + ks + tg + 4]);
            }
            #pragma unroll
            for (int ni = 0; ni < 8; ni++) {
                int nb = warpN * 64 + ni * 8 + g;
                uint32_t b0 = __float_as_uint(bs[nb * TS + ks + tg]);
                uint32_t b1 = __float_as_uint(bs[nb * TS + ks + tg + 4]);
                #pragma unroll
                for (int mi = 0; mi < 4; mi++)
                    mma_tf32(acc[mi][ni], af[mi], b0, b1);
            }
        }
        __syncthreads();   // stage may be overwritten by next iteration's load
    }

    #pragma unroll
    for (int mi = 0; mi < 4; mi++) {
        int r0g = rowBase + warpM * 64 + mi * 16 + g;
        #pragma unroll
        for (int ni = 0; ni < 8; ni++) {
            int cg = colBase + warpN * 64 + ni * 8 + tg * 2;
            if (cg < Ncols) {
                float v0 = acc[mi][ni][0], v1 = acc[mi][ni][1];
                float v2 = acc[mi][ni][2], v3 = acc[mi][ni][3];
                if (BIAS) {
                    float bx = bias[cg], by = bias[cg + 1];
                    v0 += bx; v1 += by; v2 += bx; v3 += by;
                }
                if (RES) {
                    float2 r0 = *(const float2*)(Res + (size_t)r0g * Ncols + cg);
                    float2 r1 = *(const float2*)(Res + (size_t)(r0g + 8) * Ncols + cg);
                    v0 += r0.x; v1 += r0.y; v2 += r1.x; v3 += r1.y;
                }
                if (RELU) {   // relu output feeds GEMM A -> keep tf32-clean
                    v0 = to_tf32(fmaxf(v0, 0.f)); v1 = to_tf32(fmaxf(v1, 0.f));
                    v2 = to_tf32(fmaxf(v2, 0.f)); v3 = to_tf32(fmaxf(v3, 0.f));
                }
                *(float2*)(Cc + (size_t)r0g * Ncols + cg)       = make_float2(v0, v1);
                *(float2*)(Cc + (size_t)(r0g + 8) * Ncols + cg) = make_float2(v2, v3);
            }
        }
    }
}

// ---------------- LayerNorm over C=512, one block per row ----------------
// MODE 0 (LN1): out = LN(y) exact;  outR = round(out)          (A operand for W1 GEMM)
// MODE 1 (LN2): out = LN(y) exact;  outR = round(out + qp)     (A operand for oa GEMM)
template<int MODE>
__global__ void k_ln(const float* __restrict__ y, const float* __restrict__ g,
                     const float* __restrict__ bb, float* __restrict__ out,
                     const float* __restrict__ qp, float* __restrict__ outR) {
    int row = blockIdx.x;
    int tid = threadIdx.x;   // 128
    float4 v = *(const float4*)(y + (size_t)row * CH + tid * 4);
    float s  = v.x + v.y + v.z + v.w;
    float sq = v.x * v.x + v.y * v.y + v.z * v.z + v.w * v.w;
    for (int o = 16; o > 0; o >>= 1) {
        s  += __shfl_down_sync(~0u, s,  o);
        sq += __shfl_down_sync(~0u, sq, o);
    }
    __shared__ float ss[4], ssq[4];
    __shared__ float smu, sinv;
    int wid = tid >> 5, lane = tid & 31;
    if (lane == 0) { ss[wid] = s; ssq[wid] = sq; }
    __syncthreads();
    if (tid == 0) {
        float S  = ss[0] + ss[1] + ss[2] + ss[3];
        float SQ = ssq[0] + ssq[1] + ssq[2] + ssq[3];
        float mu = S / CH;
        float var = SQ / CH - mu * mu;
        smu = mu; sinv = rsqrtf(var + 1e-5f);
    }
    __syncthreads();
    float mu = smu, inv = sinv;
    float4 gg = *(const float4*)(g  + tid * 4);
    float4 bv = *(const float4*)(bb + tid * 4);
    float4 o;
    o.x = (v.x - mu) * inv * gg.x + bv.x;
    o.y = (v.y - mu) * inv * gg.y + bv.y;
    o.z = (v.z - mu) * inv * gg.z + bv.z;
    o.w = (v.w - mu) * inv * gg.w + bv.w;
    *(float4*)(out + (size_t)row * CH + tid * 4) = o;   // exact stream
    float4 r;
    if (MODE == 0) {
        r.x = to_tf32(o.x); r.y = to_tf32(o.y);
        r.z = to_tf32(o.z); r.w = to_tf32(o.w);
    } else {
        float4 qv = *(const float4*)(qp + (size_t)row * CH + tid * 4);
        r.x = to_tf32(o.x + qv.x); r.y = to_tf32(o.y + qv.y);
        r.z = to_tf32(o.z + qv.z); r.w = to_tf32(o.w + qv.w);
    }
    *(float4*)(outR + (size_t)row * CH + tid * 4) = r;  // rounded GEMM-A stream
}

// ---------------- deformable sampling + softmax, one warp per (token, head) ----------------
__global__ void k_sample() {
    int row  = blockIdx.x;              // b*NPIX + p
    int b    = row >> 14;
    int h    = threadIdx.x >> 5;
    int lane = threadIdx.x & 31;
    float refx = g_ref[row * 2], refy = g_ref[row * 2 + 1];

    const float* oa = g_oa + (size_t)row * NOA;
    float l0 = oa[64 + h * 4 + 0];
    float l1 = oa[64 + h * 4 + 1];
    float l2 = oa[64 + h * 4 + 2];
    float l3 = oa[64 + h * 4 + 3];
    float mx = fmaxf(fmaxf(l0, l1), fmaxf(l2, l3));
    float e0 = expf(l0 - mx), e1 = expf(l1 - mx), e2 = expf(l2 - mx), e3 = expf(l3 - mx);
    float inv = 1.0f / (e0 + e1 + e2 + e3);

    const float* vb = g_v + (size_t)b * NPIX * CH + h * HDIM + lane * 2;
    float acc0 = 0.f, acc1 = 0.f;
    #pragma unroll
    for (int p = 0; p < 4; p++) {
        float wgt = (p == 0 ? e0 : p == 1 ? e1 : p == 2 ? e2 : e3) * inv;
        float ox = oa[h * 8 + p * 2 + 0];
        float oy = oa[h * 8 + p * 2 + 1];
        float x = refx * (float)WW + ox - 0.5f;
        float y = refy * (float)HH + oy - 0.5f;
        float x0f = floorf(x), y0f = floorf(y);
        float wx = x - x0f, wy = y - y0f;
        int x0 = (int)x0f, y0 = (int)y0f;
        #pragma unroll
        for (int cy = 0; cy < 2; cy++) {
            #pragma unroll
            for (int cx = 0; cx < 2; cx++) {
                int xi = x0 + cx, yi = y0 + cy;
                float wc = (cx ? wx : 1.0f - wx) * (cy ? wy : 1.0f - wy);
                float inb = (xi >= 0 && xi < WW && yi >= 0 && yi < HH) ? 1.0f : 0.0f;
                int xc = min(max(xi, 0), WW - 1);
                int yc = min(max(yi, 0), HH - 1);
                size_t base = (size_t)(yc * WW + xc) * CH;
                float w = wgt * wc * inb;
                float2 vv2 = *(const float2*)(vb + base);
                acc0 += w * vv2.x;
                acc1 += w * vv2.y;
            }
        }
    }
    *(float2*)(g_b1 + (size_t)row * CH + h * HDIM + lane * 2) =
        make_float2(to_tf32(acc0), to_tf32(acc1));
}

// ---------------- host ----------------
extern "C" void kernel_launch(void* const* d_in, const int* in_sizes, int n_in,
                              void* d_out, int out_size) {
    const float* bev   = (const float*)d_in[0];
    const float* lidar = (const float*)d_in[1];
    const float* Wv    = (const float*)d_in[2];
    const float* bv    = (const float*)d_in[3];
    const float* Woff  = (const float*)d_in[4];
    const float* boff  = (const float*)d_in[5];
    const float* Waw   = (const float*)d_in[6];
    const float* baw   = (const float*)d_in[7];
    const float* Wout  = (const float*)d_in[8];
    const float* bout  = (const float*)d_in[9];
    const float* ln1g  = (const float*)d_in[10];
    const float* ln1b  = (const float*)d_in[11];
    const float* W1    = (const float*)d_in[12];
    const float* W2    = (const float*)d_in[13];
    const float* ln2g  = (const float*)d_in[14];
    const float* ln2b  = (const float*)d_in[15];
    const float* peW1  = (const float*)d_in[16];
    const float* pbg   = (const float*)d_in[17];
    const float* pbb   = (const float*)d_in[18];
    const float* pbm   = (const float*)d_in[19];
    const float* pbv   = (const float*)d_in[20];
    const float* peW2  = (const float*)d_in[21];
    float* out = (float*)d_out;

    float *q, *qr, *qpos, *x, *feat, *vv, *b1, *b2, *oa, *wcat, *bcat;
    float *wvT, *woutT, *w1T, *w2T, *pe2T;
    cudaGetSymbolAddress((void**)&q,    g_q);
    cudaGetSymbolAddress((void**)&qr,   g_qr);
    cudaGetSymbolAddress((void**)&qpos, g_qpos);
    cudaGetSymbolAddress((void**)&x,    g_x);
    cudaGetSymbolAddress((void**)&feat, g_feat);
    cudaGetSymbolAddress((void**)&vv,   g_v);
    cudaGetSymbolAddress((void**)&b1,   g_b1);
    cudaGetSymbolAddress((void**)&b2,   g_b2);
    cudaGetSymbolAddress((void**)&oa,   g_oa);
    cudaGetSymbolAddress((void**)&wcat, g_wcat);
    cudaGetSymbolAddress((void**)&bcat, g_bcat);
    cudaGetSymbolAddress((void**)&wvT,  g_wvT);
    cudaGetSymbolAddress((void**)&woutT,g_woutT);
    cudaGetSymbolAddress((void**)&w1T,  g_w1T);
    cudaGetSymbolAddress((void**)&w2T,  g_w2T);
    cudaGetSymbolAddress((void**)&pe2T, g_pe2T);

    cudaFuncSetAttribute(k_gemm<0,0,0>, cudaFuncAttributeMaxDynamicSharedMemorySize, GEMM_SMEM);
    cudaFuncSetAttribute(k_gemm<1,0,0>, cudaFuncAttributeMaxDynamicSharedMemorySize, GEMM_SMEM);
    cudaFuncSetAttribute(k_gemm<1,1,0>, cudaFuncAttributeMaxDynamicSharedMemorySize, GEMM_SMEM);
    cudaFuncSetAttribute(k_gemm<0,0,1>, cudaFuncAttributeMaxDynamicSharedMemorySize, GEMM_SMEM);
    cudaFuncSetAttribute(k_gemm<0,1,0>, cudaFuncAttributeMaxDynamicSharedMemorySize, GEMM_SMEM);

    dim3 trb(32, 8);
    // weight pre-transposes (rounded to tf32): [512,512] -> [512,512]^T, layers via z
    k_tr<1><<<dim3(16, 16, LNUM), trb>>>(Wv,   wvT,   512, 512);
    k_tr<1><<<dim3(16, 16, LNUM), trb>>>(Wout, woutT, 512, 512);
    k_tr<1><<<dim3(16, 16, LNUM), trb>>>(W1,   w1T,   512, 512);
    k_tr<1><<<dim3(16, 16, LNUM), trb>>>(W2,   w2T,   512, 512);
    k_tr<1><<<dim3(16, 16, 1),    trb>>>(peW2, pe2T,  512, 512);
    k_concat<<<(LNUM * NOA * CH + 255) / 256, 256>>>(Woff, boff, Waw, baw);

    // lidar (B,C,N) -> b2 (B,N,C) [exact]; validity; packed q [exact]
    k_tr<0><<<dim3(NPIX / 32, CH / 32, BATCH), trb>>>(lidar, b2, CH, NPIX);
    k_validity<<<MROWS, 128>>>(b2);
    k_scan<<<BATCH, 1024>>>();
    k_ref<<<MROWS / 256, 256>>>();
    k_permq<<<MROWS * 128 / 256, 256>>>(b2, q);
    // bev (B,C,N) -> feat (B,N,C) [rounded: GEMM A operand]
    k_tr<1><<<dim3(NPIX / 32, CH / 32, BATCH), trb>>>(bev, feat, CH, NPIX);
    k_pe<<<MROWS * CH / 256, 256>>>(peW1, pbg, pbb, pbm, pbv);

    dim3 g512(4, MROWS / 128), g96(1, MROWS / 128);
    // q_pos = relu(pe) @ peW2
    k_gemm<0,0,0><<<g512, 128, GEMM_SMEM>>>(b1, pe2T, nullptr, nullptr, qpos, 512);
    // x = round(q + qpos)
    k_add<<<MROWS * 128 / 256, 256>>>(q, qpos, x);

    for (int i = 0; i < LNUM; i++) {
        const float* WvTi   = wvT   + (size_t)i * CH * CH;
        const float* WcatTi = wcat  + (size_t)i * NOA * CH;
        const float* WoutTi = woutT + (size_t)i * CH * CH;
        const float* W1Ti   = w1T   + (size_t)i * CH * CH;
        const float* W2Ti   = w2T   + (size_t)i * CH * CH;

        // v = feat @ Wv + bv
        k_gemm<1,0,0><<<g512, 128, GEMM_SMEM>>>(feat, WvTi, bv + i * CH, nullptr, vv, 512);
        // [off | aw-logits] = x @ Wcat + bcat
        k_gemm<1,0,0><<<g96, 128, GEMM_SMEM>>>(x, WcatTi, bcat + i * NOA, nullptr, oa, NOA);
        // deformable sampling -> b1
        k_sample<<<MROWS, 256>>>();
        // y = b1 @ Wout + bout + q(exact) ; q = LN1(y) exact, qr = round(q)
        k_gemm<1,1,0><<<g512, 128, GEMM_SMEM>>>(b1, WoutTi, bout + i * CH, q, b2, 512);
        k_ln<0><<<MROWS, 128>>>(b2, ln1g + i * CH, ln1b + i * CH, q, nullptr, qr);
        // FFN: b1 = relu(qr@W1); y2 = b1@W2 + q(exact); q = LN2(y2) exact, x = round(q+qpos)
        k_gemm<0,0,1><<<g512, 128, GEMM_SMEM>>>(qr, W1Ti, nullptr, nullptr, b1, 512);
        k_gemm<0,1,0><<<g512, 128, GEMM_SMEM>>>(b1, W2Ti, nullptr, q,       b2, 512);
        k_ln<1><<<MROWS, 128>>>(b2, ln2g + i * CH, ln2b + i * CH, q, qpos, x);
    }
    // q (packed, exact) -> dense rows in b2 (B,N,C) -> transpose to out (B,C,N)
    k_scatrows<<<MROWS * 128 / 256, 256>>>(q, b2);
    k_tr<0><<<dim3(CH / 32, NPIX / 32, BATCH), trb>>>(b2, out, NPIX, CH);
}

// round 17
// speedup vs baseline: 1.3803x; 1.3803x over previous
#include <cuda_runtime.h>
#include <cuda_fp16.h>
#include <math.h>
#include <stdint.h>

#define BATCH 2
#define CH    512
#define HH    128
#define WW    128
#define NPIX  (HH*WW)        // 16384
#define MROWS (BATCH*NPIX)   // 32768
#define HEADS 8
#define HDIM  64
#define PTS   4
#define LNUM  6
#define NOA   96             // 64 offset cols + 32 attn cols

// ---------------- device scratch (no allocations allowed) ----------------
static __device__ float  g_q   [MROWS*CH];   // exact residual stream
static __device__ float  g_qpos[MROWS*CH];   // exact
static __device__ float  g_b2  [MROWS*CH];   // LN inputs / staging
static __device__ float  g_oa  [MROWS*NOA];
static __device__ float  g_ref [MROWS*2];
static __device__ __half g_feat_h[MROWS*CH]; // GEMM A operands (fp16)
static __device__ __half g_v_h   [MROWS*CH];
static __device__ __half g_b1h   [MROWS*CH];
static __device__ __half g_qr_h  [MROWS*CH];
static __device__ __half g_x_h   [MROWS*CH];
static __device__ __half g_wvT_h  [LNUM*CH*CH];  // weights [l][n][k] fp16
static __device__ __half g_woutT_h[LNUM*CH*CH];
static __device__ __half g_w1T_h  [LNUM*CH*CH];
static __device__ __half g_w2T_h  [LNUM*CH*CH];
static __device__ __half g_wcat_h [LNUM*NOA*CH];
static __device__ __half g_pe2T_h [CH*CH];
static __device__ float  g_bcat[LNUM*NOA];
static __device__ int    g_valid [MROWS];
static __device__ int    g_order [MROWS];
static __device__ int    g_validp[MROWS];
static __device__ int    g_rank  [MROWS];

__device__ __forceinline__ uint32_t smem_u32(const void* p) {
    uint32_t a;
    asm("{ .reg .u64 t; cvta.to.shared.u64 t, %1; cvt.u32.u64 %0, t; }" : "=r"(a) : "l"(p));
    return a;
}
__device__ __forceinline__ void cpa16(uint32_t s, const void* g) {
    asm volatile("cp.async.cg.shared.global [%0], [%1], 16;" :: "r"(s), "l"(g));
}

// ---------------- tiled transpose fp32: src[B][R][Cc] -> dst[B][Cc][R] ----------------
__global__ void k_tr(const float* __restrict__ src, float* __restrict__ dst, int R, int Cc) {
    __shared__ float t[32][33];
    int b  = blockIdx.z;
    int c0 = blockIdx.x * 32, r0 = blockIdx.y * 32;
    int tx = threadIdx.x, ty = threadIdx.y;   // 32 x 8
    const float* s = src + (size_t)b * R * Cc;
    float*       d = dst + (size_t)b * R * Cc;
    #pragma unroll
    for (int i = 0; i < 32; i += 8)
        t[ty + i][tx] = s[(size_t)(r0 + ty + i) * Cc + c0 + tx];
    __syncthreads();
    #pragma unroll
    for (int i = 0; i < 32; i += 8)
        d[(size_t)(c0 + ty + i) * R + r0 + tx] = t[tx][ty + i];
}

// ---------------- tiled transpose fp32 -> fp16 ----------------
__global__ void k_trh(const float* __restrict__ src, __half* __restrict__ dst, int R, int Cc) {
    __shared__ float t[32][33];
    int b  = blockIdx.z;
    int c0 = blockIdx.x * 32, r0 = blockIdx.y * 32;
    int tx = threadIdx.x, ty = threadIdx.y;
    const float* s = src + (size_t)b * R * Cc;
    __half*      d = dst + (size_t)b * R * Cc;
    #pragma unroll
    for (int i = 0; i < 32; i += 8)
        t[ty + i][tx] = s[(size_t)(r0 + ty + i) * Cc + c0 + tx];
    __syncthreads();
    #pragma unroll
    for (int i = 0; i < 32; i += 8)
        d[(size_t)(c0 + ty + i) * R + r0 + tx] = __float2half(t[tx][ty + i]);
}

// ---------------- validity from row-major [B][N][C]: all 512 nonzero ----------------
__global__ void k_validity(const float* __restrict__ t) {
    int row = blockIdx.x;
    int tid = threadIdx.x;          // 128
    float4 v = *(const float4*)(t + (size_t)row * CH + tid * 4);
    int ok = (v.x != 0.0f) & (v.y != 0.0f) & (v.z != 0.0f) & (v.w != 0.0f);
    ok = __all_sync(~0u, ok);
    __shared__ int s[4];
    if ((tid & 31) == 0) s[tid >> 5] = ok;
    __syncthreads();
    if (tid == 0) g_valid[row] = s[0] & s[1] & s[2] & s[3];
}

// ---------------- stable partition (valid-first) via block scan ----------------
__global__ void k_scan() {
    int b = blockIdx.x;
    int tid = threadIdx.x;
    __shared__ int sd[1024];
    __shared__ int sbase;
    if (tid == 0) sbase = 0;
    __syncthreads();
    for (int c = 0; c < NPIX / 1024; c++) {
        int i = c * 1024 + tid;
        int v = g_valid[b * NPIX + i];
        sd[tid] = v;
        __syncthreads();
        for (int off = 1; off < 1024; off <<= 1) {
            int t = (tid >= off) ? sd[tid - off] : 0;
            __syncthreads();
            sd[tid] += t;
            __syncthreads();
        }
        g_rank[b * NPIX + i] = sbase + sd[tid] - v;
        __syncthreads();
        if (tid == 1023) sbase += sd[1023];
        __syncthreads();
    }
    int total = sbase;
    for (int c = 0; c < NPIX / 1024; c++) {
        int i = c * 1024 + tid;
        int v = g_valid[b * NPIX + i];
        int r = g_rank[b * NPIX + i];
        int pos = v ? r : (total + i - r);
        g_order [b * NPIX + pos] = i;
        g_validp[b * NPIX + pos] = v;
    }
}

__global__ void k_ref() {
    int i = blockIdx.x * blockDim.x + threadIdx.x;
    if (i >= MROWS) return;
    int n = g_order[i];
    float m = g_validp[i] ? 1.0f : 0.0f;
    g_ref[i * 2 + 0] = ((float)(n % WW) / (float)WW) * m;
    g_ref[i * 2 + 1] = ((float)(n / WW) / (float)HH) * m;
}

// ---------------- permute rows of [B][N][C] into packed order (exact fp32) ----------------
__global__ void k_permq(const float* __restrict__ t, float* __restrict__ dst) {
    int idx = blockIdx.x * blockDim.x + threadIdx.x;   // float4 units
    if (idx >= MROWS * 128) return;
    int row = idx >> 7, c4 = idx & 127;
    int n = g_order[row];
    int b = row >> 14;
    float4 v = make_float4(0.f, 0.f, 0.f, 0.f);
    if (g_validp[row])
        v = *(const float4*)(t + ((size_t)(b * NPIX + n)) * CH + c4 * 4);
    *(float4*)(dst + (size_t)row * CH + c4 * 4) = v;
}

// ---------------- scatter packed rows back to dense [B][N][C] ----------------
__global__ void k_scatrows(const float* __restrict__ q, float* __restrict__ t) {
    int idx = blockIdx.x * blockDim.x + threadIdx.x;
    if (idx >= MROWS * 128) return;
    int row = idx >> 7, c4 = idx & 127;
    int n = g_order[row];
    int b = row >> 14;
    float4 v = make_float4(0.f, 0.f, 0.f, 0.f);
    if (g_validp[row])
        v = *(const float4*)(q + (size_t)row * CH + c4 * 4);
    *(float4*)(t + ((size_t)(b * NPIX + n)) * CH + c4 * 4) = v;
}

// ---------------- x_h = half(a + b) ----------------
__global__ void k_add(const float* __restrict__ a, const float* __restrict__ b,
                      __half* __restrict__ o) {
    int idx = blockIdx.x * blockDim.x + threadIdx.x;
    if (idx >= MROWS * 128) return;
    float4 va = *(const float4*)(a + (size_t)idx * 4);
    float4 vb = *(const float4*)(b + (size_t)idx * 4);
    __half2 h0 = __floats2half2_rn(va.x + vb.x, va.y + vb.y);
    __half2 h1 = __floats2half2_rn(va.z + vb.z, va.w + vb.w);
    ((__half2*)o)[idx * 2]     = h0;
    ((__half2*)o)[idx * 2 + 1] = h1;
}

// ---------------- concat Woff|Waw -> transposed half [l][n][k] + biases ----------------
__global__ void k_concat(const float* __restrict__ Woff, const float* __restrict__ boff,
                         const float* __restrict__ Waw,  const float* __restrict__ baw) {
    int idx = blockIdx.x * blockDim.x + threadIdx.x;
    if (idx < LNUM * NOA * CH) {
        int k = idx & (CH - 1);
        int j = (idx >> 9) % NOA;
        int l = idx / (NOA * CH);
        float w = (j < 64) ? Woff[((size_t)l * CH + k) * 64 + j]
                           : Waw [((size_t)l * CH + k) * 32 + (j - 64)];
        g_wcat_h[idx] = __float2half(w);
    }
    if (idx < LNUM * NOA) {
        int j = idx % NOA, l = idx / NOA;
        g_bcat[idx] = (j < 64) ? boff[l * 64 + j] : baw[l * 32 + (j - 64)];
    }
}

// ---------------- positional embedding -> b1h (fp16) ----------------
__global__ void k_pe(const float* __restrict__ peW1, const float* __restrict__ g,
                     const float* __restrict__ bb, const float* __restrict__ m,
                     const float* __restrict__ vv) {
    int idx = blockIdx.x * blockDim.x + threadIdx.x;
    if (idx >= MROWS * CH) return;
    int c   = idx & (CH - 1);
    int row = idx >> 9;
    float rx = g_ref[row * 2], ry = g_ref[row * 2 + 1];
    float p = rx * peW1[c] + ry * peW1[CH + c];
    p = (p - m[c]) * rsqrtf(vv[c] + 1e-5f) * g[c] + bb[c];
    g_b1h[idx] = __float2half(fmaxf(p, 0.0f));
}

// ================= fp16 mma.sync GEMM (m16n8k16), 64x64 warp tiles, cp.async 2-stage =================
// C[M,Ncols] = A[M,512] @ Bt[Ncols,512]^T  (+bias)(+Res)(relu?) -> fp32 Cf or fp16 Ch
// CTA tile 128x128, 4 warps (2x2) of 64x64, BK=32.
// Tiles K-major [128 rows][32 halves], row stride 40 halves (=80B, 16B-aligned;
// LDS word bank pattern (20g+tg)%32 all distinct -> conflict-free).
__device__ __forceinline__ void mma_f16(float c[4], const uint32_t a[4],
                                        uint32_t b0, uint32_t b1) {
    asm volatile(
        "mma.sync.aligned.m16n8k16.row.col.f32.f16.f16.f32 "
        "{%0,%1,%2,%3}, {%4,%5,%6,%7}, {%8,%9}, {%0,%1,%2,%3};"
        : "+f"(c[0]), "+f"(c[1]), "+f"(c[2]), "+f"(c[3])
        : "r"(a[0]), "r"(a[1]), "r"(a[2]), "r"(a[3]), "r"(b0), "r"(b1));
}

#define HTS 40   // tile row stride in halves

template<int BIAS, int RES, int RELU, int HOUT>
__global__ __launch_bounds__(128)
void k_gemm(const __half* __restrict__ A, const __half* __restrict__ Bt,
            const float* __restrict__ bias, const float* __restrict__ Res,
            float* __restrict__ Cf, __half* __restrict__ Ch, int Ncols) {
    __shared__ __align__(16) __half smA[2][128 * HTS];
    __shared__ __align__(16) __half smB[2][128 * HTS];
    int tid  = threadIdx.x;
    int warp = tid >> 5, lane = tid & 31;
    int g    = lane >> 2, tg = lane & 3;
    int warpM = warp & 1;
    int warpN = warp >> 1;
    int rowBase = blockIdx.y * 128;
    int colBase = blockIdx.x * 128;
    int nValid = Ncols - colBase; if (nValid > 128) nValid = 128;

    // per-thread load geometry: 4 x 16B chunks per operand per tile
    int ldr = tid >> 2;                  // row 0..31 (advance +32 per p)
    int lch = (tid & 3) << 3;            // half offset within row (0,8,16,24)

    auto load_tile = [&](int t) {
        int s = t & 1;
        int k0 = t * 32;
        __half* as = smA[s];
        __half* bs = smB[s];
        #pragma unroll
        for (int p = 0; p < 4; p++) {
            int r = ldr + p * 32;
            cpa16(smem_u32(&as[r * HTS + lch]),
                  A + (size_t)(rowBase + r) * 512 + k0 + lch);
            uint32_t sb = smem_u32(&bs[r * HTS + lch]);
            if (r < nValid)
                cpa16(sb, Bt + (size_t)(colBase + r) * 512 + k0 + lch);
            else
                asm volatile("st.shared.v4.b32 [%0], {%1,%1,%1,%1};" :: "r"(sb), "r"(0u));
        }
        asm volatile("cp.async.commit_group;");
    };

    float acc[4][8][4];
    #pragma unroll
    for (int mi = 0; mi < 4; mi++)
        #pragma unroll
        for (int ni = 0; ni < 8; ni++)
            #pragma unroll
            for (int j = 0; j < 4; j++) acc[mi][ni][j] = 0.0f;

    load_tile(0);

    #pragma unroll 1
    for (int t = 0; t < 16; t++) {
        if (t < 15) {
            load_tile(t + 1);
            asm volatile("cp.async.wait_group 1;" ::: "memory");
        } else {
            asm volatile("cp.async.wait_group 0;" ::: "memory");
        }
        __syncthreads();
        const uint32_t* as32 = (const uint32_t*)smA[t & 1];
        const uint32_t* bs32 = (const uint32_t*)smB[t & 1];
        #pragma unroll
        for (int kk = 0; kk < 2; kk++) {
            int ko = kk * 8;   // word offset (16 halves per k-step)
            uint32_t af[4][4];
            #pragma unroll
            for (int mi = 0; mi < 4; mi++) {
                int rb = warpM * 64 + mi * 16 + g;
                af[mi][0] = as32[rb * 20 + ko + tg];
                af[mi][1] = as32[(rb + 8) * 20 + ko + tg];
                af[mi][2] = as32[rb * 20 + ko + 4 + tg];
                af[mi][3] = as32[(rb + 8) * 20 + ko + 4 + tg];
            }
            #pragma unroll
            for (int ni = 0; ni < 8; ni++) {
                int nb = warpN * 64 + ni * 8 + g;
                uint32_t b0 = bs32[nb * 20 + ko + tg];
                uint32_t b1 = bs32[nb * 20 + ko + 4 + tg];
                #pragma unroll
                for (int mi = 0; mi < 4; mi++)
                    mma_f16(acc[mi][ni], af[mi], b0, b1);
            }
        }
        __syncthreads();
    }

    #pragma unroll
    for (int mi = 0; mi < 4; mi++) {
        int r0g = rowBase + warpM * 64 + mi * 16 + g;
        #pragma unroll
        for (int ni = 0; ni < 8; ni++) {
            int cg = colBase + warpN * 64 + ni * 8 + tg * 2;
            if (cg < Ncols) {
                float v0 = acc[mi][ni][0], v1 = acc[mi][ni][1];
                float v2 = acc[mi][ni][2], v3 = acc[mi][ni][3];
                if (BIAS) {
                    float bx = bias[cg], by = bias[cg + 1];
                    v0 += bx; v1 += by; v2 += bx; v3 += by;
                }
                if (RES) {
                    float2 r0 = *(const float2*)(Res + (size_t)r0g * Ncols + cg);
                    float2 r1 = *(const float2*)(Res + (size_t)(r0g + 8) * Ncols + cg);
                    v0 += r0.x; v1 += r0.y; v2 += r1.x; v3 += r1.y;
                }
                if (RELU) {
                    v0 = fmaxf(v0, 0.f); v1 = fmaxf(v1, 0.f);
                    v2 = fmaxf(v2, 0.f); v3 = fmaxf(v3, 0.f);
                }
                if (HOUT) {
                    *(__half2*)(Ch + (size_t)r0g * Ncols + cg) = __floats2half2_rn(v0, v1);
                    *(__half2*)(Ch + (size_t)(r0g + 8) * Ncols + cg) = __floats2half2_rn(v2, v3);
                } else {
                    *(float2*)(Cf + (size_t)r0g * Ncols + cg)       = make_float2(v0, v1);
                    *(float2*)(Cf + (size_t)(r0g + 8) * Ncols + cg) = make_float2(v2, v3);
                }
            }
        }
    }
}

// ---------------- LayerNorm over C=512, one block per row ----------------
// MODE 0 (LN1): out = LN(y) exact fp32;  outR = half(out)       (A for W1 GEMM)
// MODE 1 (LN2): out = LN(y) exact fp32;  outR = half(out + qp)  (A for oa GEMM)
template<int MODE>
__global__ void k_ln(const float* __restrict__ y, const float* __restrict__ g,
                     const float* __restrict__ bb, float* __restrict__ out,
                     const float* __restrict__ qp, __half* __restrict__ outR) {
    int row = blockIdx.x;
    int tid = threadIdx.x;   // 128
    float4 v = *(const float4*)(y + (size_t)row * CH + tid * 4);
    float s  = v.x + v.y + v.z + v.w;
    float sq = v.x * v.x + v.y * v.y + v.z * v.z + v.w * v.w;
    for (int o = 16; o > 0; o >>= 1) {
        s  += __shfl_down_sync(~0u, s,  o);
        sq += __shfl_down_sync(~0u, sq, o);
    }
    __shared__ float ss[4], ssq[4];
    __shared__ float smu, sinv;
    int wid = tid >> 5, lane = tid & 31;
    if (lane == 0) { ss[wid] = s; ssq[wid] = sq; }
    __syncthreads();
    if (tid == 0) {
        float S  = ss[0] + ss[1] + ss[2] + ss[3];
        float SQ = ssq[0] + ssq[1] + ssq[2] + ssq[3];
        float mu = S / CH;
        float var = SQ / CH - mu * mu;
        smu = mu; sinv = rsqrtf(var + 1e-5f);
    }
    __syncthreads();
    float mu = smu, inv = sinv;
    float4 gg = *(const float4*)(g  + tid * 4);
    float4 bv = *(const float4*)(bb + tid * 4);
    float4 o;
    o.x = (v.x - mu) * inv * gg.x + bv.x;
    o.y = (v.y - mu) * inv * gg.y + bv.y;
    o.z = (v.z - mu) * inv * gg.z + bv.z;
    o.w = (v.w - mu) * inv * gg.w + bv.w;
    *(float4*)(out + (size_t)row * CH + tid * 4) = o;   // exact stream
    __half2 h0, h1;
    if (MODE == 0) {
        h0 = __floats2half2_rn(o.x, o.y);
        h1 = __floats2half2_rn(o.z, o.w);
    } else {
        float4 qv = *(const float4*)(qp + (size_t)row * CH + tid * 4);
        h0 = __floats2half2_rn(o.x + qv.x, o.y + qv.y);
        h1 = __floats2half2_rn(o.z + qv.z, o.w + qv.w);
    }
    ((__half2*)(outR + (size_t)row * CH))[tid * 2]     = h0;
    ((__half2*)(outR + (size_t)row * CH))[tid * 2 + 1] = h1;
}

// ---------------- deformable sampling + softmax, one warp per (token, head) ----------------
__global__ void k_sample() {
    int row  = blockIdx.x;              // b*NPIX + p
    int b    = row >> 14;
    int h    = threadIdx.x >> 5;
    int lane = threadIdx.x & 31;
    float refx = g_ref[row * 2], refy = g_ref[row * 2 + 1];

    const float* oa = g_oa + (size_t)row * NOA;
    float l0 = oa[64 + h * 4 + 0];
    float l1 = oa[64 + h * 4 + 1];
    float l2 = oa[64 + h * 4 + 2];
    float l3 = oa[64 + h * 4 + 3];
    float mx = fmaxf(fmaxf(l0, l1), fmaxf(l2, l3));
    float e0 = expf(l0 - mx), e1 = expf(l1 - mx), e2 = expf(l2 - mx), e3 = expf(l3 - mx);
    float inv = 1.0f / (e0 + e1 + e2 + e3);

    const __half* vb = g_v_h + (size_t)b * NPIX * CH + h * HDIM + lane * 2;
    float acc0 = 0.f, acc1 = 0.f;
    #pragma unroll
    for (int p = 0; p < 4; p++) {
        float wgt = (p == 0 ? e0 : p == 1 ? e1 : p == 2 ? e2 : e3) * inv;
        float ox = oa[h * 8 + p * 2 + 0];
        float oy = oa[h * 8 + p * 2 + 1];
        float x = refx * (float)WW + ox - 0.5f;
        float y = refy * (float)HH + oy - 0.5f;
        float x0f = floorf(x), y0f = floorf(y);
        float wx = x - x0f, wy = y - y0f;
        int x0 = (int)x0f, y0 = (int)y0f;
        #pragma unroll
        for (int cy = 0; cy < 2; cy++) {
            #pragma unroll
            for (int cx = 0; cx < 2; cx++) {
                int xi = x0 + cx, yi = y0 + cy;
                float wc = (cx ? wx : 1.0f - wx) * (cy ? wy : 1.0f - wy);
                float inb = (xi >= 0 && xi < WW && yi >= 0 && yi < HH) ? 1.0f : 0.0f;
                int xc = min(max(xi, 0), WW - 1);
                int yc = min(max(yi, 0), HH - 1);
                size_t base = (size_t)(yc * WW + xc) * CH;
                float w = wgt * wc * inb;
                float2 vv2 = __half22float2(*(const __half2*)(vb + base));
                acc0 += w * vv2.x;
                acc1 += w * vv2.y;
            }
        }
    }
    *(__half2*)(g_b1h + (size_t)row * CH + h * HDIM + lane * 2) =
        __floats2half2_rn(acc0, acc1);
}

// ---------------- host ----------------
extern "C" void kernel_launch(void* const* d_in, const int* in_sizes, int n_in,
                              void* d_out, int out_size) {
    const float* bev   = (const float*)d_in[0];
    const float* lidar = (const float*)d_in[1];
    const float* Wv    = (const float*)d_in[2];
    const float* bv    = (const float*)d_in[3];
    const float* Woff  = (const float*)d_in[4];
    const float* boff  = (const float*)d_in[5];
    const float* Waw   = (const float*)d_in[6];
    const float* baw   = (const float*)d_in[7];
    const float* Wout  = (const float*)d_in[8];
    const float* bout  = (const float*)d_in[9];
    const float* ln1g  = (const float*)d_in[10];
    const float* ln1b  = (const float*)d_in[11];
    const float* W1    = (const float*)d_in[12];
    const float* W2    = (const float*)d_in[13];
    const float* ln2g  = (const float*)d_in[14];
    const float* ln2b  = (const float*)d_in[15];
    const float* peW1  = (const float*)d_in[16];
    const float* pbg   = (const float*)d_in[17];
    const float* pbb   = (const float*)d_in[18];
    const float* pbm   = (const float*)d_in[19];
    const float* pbv   = (const float*)d_in[20];
    const float* peW2  = (const float*)d_in[21];
    float* out = (float*)d_out;

    float *q, *qpos, *b2, *oa, *bcat;
    __half *feat_h, *v_h, *b1h, *qr_h, *x_h;
    __half *wvT_h, *woutT_h, *w1T_h, *w2T_h, *wcat_h, *pe2T_h;
    cudaGetSymbolAddress((void**)&q,      g_q);
    cudaGetSymbolAddress((void**)&qpos,   g_qpos);
    cudaGetSymbolAddress((void**)&b2,     g_b2);
    cudaGetSymbolAddress((void**)&oa,     g_oa);
    cudaGetSymbolAddress((void**)&bcat,   g_bcat);
    cudaGetSymbolAddress((void**)&feat_h, g_feat_h);
    cudaGetSymbolAddress((void**)&v_h,    g_v_h);
    cudaGetSymbolAddress((void**)&b1h,    g_b1h);
    cudaGetSymbolAddress((void**)&qr_h,   g_qr_h);
    cudaGetSymbolAddress((void**)&x_h,    g_x_h);
    cudaGetSymbolAddress((void**)&wvT_h,  g_wvT_h);
    cudaGetSymbolAddress((void**)&woutT_h,g_woutT_h);
    cudaGetSymbolAddress((void**)&w1T_h,  g_w1T_h);
    cudaGetSymbolAddress((void**)&w2T_h,  g_w2T_h);
    cudaGetSymbolAddress((void**)&wcat_h, g_wcat_h);
    cudaGetSymbolAddress((void**)&pe2T_h, g_pe2T_h);

    dim3 trb(32, 8);
    // weight pre-transposes to fp16 [n][k], layers batched via z
    k_trh<<<dim3(16, 16, LNUM), trb>>>(Wv,   wvT_h,   512, 512);
    k_trh<<<dim3(16, 16, LNUM), trb>>>(Wout, woutT_h, 512, 512);
    k_trh<<<dim3(16, 16, LNUM), trb>>>(W1,   w1T_h,   512, 512);
    k_trh<<<dim3(16, 16, LNUM), trb>>>(W2,   w2T_h,   512, 512);
    k_trh<<<dim3(16, 16, 1),    trb>>>(peW2, pe2T_h,  512, 512);
    k_concat<<<(LNUM * NOA * CH + 255) / 256, 256>>>(Woff, boff, Waw, baw);

    // lidar (B,C,N) -> b2 (B,N,C) [exact]; validity; packed q [exact]
    k_tr<<<dim3(NPIX / 32, CH / 32, BATCH), trb>>>(lidar, b2, CH, NPIX);
    k_validity<<<MROWS, 128>>>(b2);
    k_scan<<<BATCH, 1024>>>();
    k_ref<<<MROWS / 256, 256>>>();
    k_permq<<<MROWS * 128 / 256, 256>>>(b2, q);
    // bev (B,C,N) -> feat_h (B,N,C) fp16 (GEMM A)
    k_trh<<<dim3(NPIX / 32, CH / 32, BATCH), trb>>>(bev, feat_h, CH, NPIX);
    k_pe<<<MROWS * CH / 256, 256>>>(peW1, pbg, pbb, pbm, pbv);

    dim3 g512(4, MROWS / 128), g96(1, MROWS / 128);
    // q_pos = relu(pe) @ peW2  (fp32 out)
    k_gemm<0,0,0,0><<<g512, 128>>>(b1h, pe2T_h, nullptr, nullptr, qpos, nullptr, 512);
    // x_h = half(q + qpos)
    k_add<<<MROWS * 128 / 256, 256>>>(q, qpos, x_h);

    for (int i = 0; i < LNUM; i++) {
        const __half* WvTi   = wvT_h   + (size_t)i * CH * CH;
        const __half* WcatTi = wcat_h  + (size_t)i * NOA * CH;
        const __half* WoutTi = woutT_h + (size_t)i * CH * CH;
        const __half* W1Ti   = w1T_h   + (size_t)i * CH * CH;
        const __half* W2Ti   = w2T_h   + (size_t)i * CH * CH;

        // v = feat @ Wv + bv  (fp16 out for sampler)
        k_gemm<1,0,0,1><<<g512, 128>>>(feat_h, WvTi, bv + i * CH, nullptr, nullptr, v_h, 512);
        // [off | aw-logits] = x @ Wcat + bcat  (fp32 out)
        k_gemm<1,0,0,0><<<g96, 128>>>(x_h, WcatTi, bcat + i * NOA, nullptr, oa, nullptr, NOA);
        // deformable sampling -> b1h
        k_sample<<<MROWS, 256>>>();
        // y = b1 @ Wout + bout + q(exact) ; q = LN1(y) exact, qr_h = half(q)
        k_gemm<1,1,0,0><<<g512, 128>>>(b1h, WoutTi, bout + i * CH, q, b2, nullptr, 512);
        k_ln<0><<<MROWS, 128>>>(b2, ln1g + i * CH, ln1b + i * CH, q, nullptr, qr_h);
        // FFN: b1h = half(relu(qr@W1)); y2 = b1@W2 + q(exact); q = LN2 exact, x_h = half(q+qpos)
        k_gemm<0,0,1,1><<<g512, 128>>>(qr_h, W1Ti, nullptr, nullptr, nullptr, b1h, 512);
        k_gemm<0,1,0,0><<<g512, 128>>>(b1h, W2Ti, nullptr, q, b2, nullptr, 512);
        k_ln<1><<<MROWS, 128>>>(b2, ln2g + i * CH, ln2b + i * CH, q, qpos, x_h);
    }
    // q (packed, exact) -> dense rows in b2 (B,N,C) -> transpose to out (B,C,N)
    k_scatrows<<<MROWS * 128 / 256, 256>>>(q, b2);
    k_tr<<<dim3(CH / 32, NPIX / 32, BATCH), trb>>>(b2, out, NPIX, CH);
}